// round 1
// baseline (speedup 1.0000x reference)
#include <cuda_runtime.h>
#include <cuda_bf16.h>

#define BB 1024
#define TT 512
#define KK 48
#define CPB 2   // chains per block

// Scratch (static __device__ globals: allocation-free per harness rules)
__device__ float g_expTt[KK * KK];  // transposed exp(transitions): [j][i]
__device__ float g_den[BB];
__device__ float g_num[BB];

// ---------------------------------------------------------------------------
// Precompute exp(transitions) transposed so thread j's column is contiguous.
// ---------------------------------------------------------------------------
__global__ void crf_prep_kernel(const float* __restrict__ trans) {
    int idx = blockIdx.x * blockDim.x + threadIdx.x;
    if (idx < KK * KK) {
        int j = idx / KK;
        int i = idx - j * KK;
        g_expTt[idx] = expf(trans[i * KK + j]);   // accurate expf, runs once
    }
}

// ---------------------------------------------------------------------------
// Main: forward algorithm (log_den) + gold path score (log_num), per chain.
// Block = CPB chains x KK threads. Thread j owns state j of its chain.
// State alpha[j] is stored as s[j] (float, renormalized) + C (double offset).
// ---------------------------------------------------------------------------
__global__ __launch_bounds__(CPB * KK) void crf_main_kernel(
    const float* __restrict__ em,      // [B,T,K]
    const int*   __restrict__ tags,    // [B,T]
    const float* __restrict__ mask,    // [B,T]
    const float* __restrict__ trans,   // [K,K]
    const float* __restrict__ startT,  // [K]
    const float* __restrict__ endT)    // [K]
{
    const int c = threadIdx.x / KK;
    const int j = threadIdx.x - c * KK;
    const int b = blockIdx.x * CPB + c;

    __shared__ float sh_a[CPB][KK];
    __shared__ float sh_p[CPB][KK];

    const float* emb = em   + (size_t)b * TT * KK;
    const float* mkb = mask + (size_t)b * TT;

    // exp(T[i][j]) column for this thread's output state j -> registers
    float ET[KK];
#pragma unroll
    for (int i = 0; i < KK; i++) ET[i] = g_expTt[j * KK + i];

    // alpha0 = start + emissions[:,0]
    float  s = startT[j] + emb[j];
    double C = 0.0;

    const float LOG2E = 1.4426950408889634f;
    const float LN2   = 0.6931471805599453f;

    float e_next = emb[KK + j];   // prefetch t=1
#pragma unroll 1
    for (int t = 1; t < TT; t++) {
        float e = e_next;
        int tn = (t + 1 < TT) ? (t + 1) : (TT - 1);
        e_next = emb[tn * KK + j];                  // prefetch next step
        float mk = mkb[t];

        float a = s + e;
        sh_a[c][j] = a;
        __syncthreads();
        float m = sh_a[c][0];                       // cheap reference element
        sh_p[c][j] = exp2f((a - m) * LOG2E);        // MUFU.EX2
        __syncthreads();

        float acc0 = 0.f, acc1 = 0.f, acc2 = 0.f, acc3 = 0.f;
#pragma unroll
        for (int i = 0; i < KK; i += 4) {           // LDS broadcast + FFMA
            acc0 = fmaf(sh_p[c][i + 0], ET[i + 0], acc0);
            acc1 = fmaf(sh_p[c][i + 1], ET[i + 1], acc1);
            acc2 = fmaf(sh_p[c][i + 2], ET[i + 2], acc2);
            acc3 = fmaf(sh_p[c][i + 3], ET[i + 3], acc3);
        }
        float acc = (acc0 + acc1) + (acc2 + acc3);
        float l = log2f(acc) * LN2;                 // MUFU.LG2

        if (mk != 0.f) { s = l;   C += (double)m; } // alpha = C + m + log(acc)
        else           { s = 0.f; C = 0.0;        } // alpha *= 0 (mask)
    }

    // log_den[b] = C + LSE_j(s[j] + end[j])
    sh_a[c][j] = s + endT[j];
    __syncthreads();
    if (j == 0) {
        float mm = sh_a[c][0];
#pragma unroll
        for (int i = 1; i < KK; i++) mm = fmaxf(mm, sh_a[c][i]);
        float ss = 0.f;
#pragma unroll
        for (int i = 0; i < KK; i++) ss += exp2f((sh_a[c][i] - mm) * LOG2E);
        g_den[b] = (float)(C + (double)(mm + log2f(ss) * LN2));
    }
    __syncthreads();

    // log_num[b]: gold path score (strided over t, fixed-order reduce)
    const int* tg = tags + (size_t)b * TT;
    float part = 0.f, msum = 0.f;
    for (int t = j; t < TT - 1; t += KK) {
        int t0 = tg[t], t1 = tg[t + 1];
        part += emb[t * KK + t0];
        part += trans[t0 * KK + t1] * mkb[t + 1];
    }
    for (int t = j; t < TT; t += KK) msum += mkb[t];
    sh_a[c][j] = part;
    sh_p[c][j] = msum;
    __syncthreads();
    if (j == 0) {
        float tot = 0.f, mtot = 0.f;
        for (int i = 0; i < KK; i++) { tot += sh_a[c][i]; mtot += sh_p[c][i]; }
        int last = (int)mtot - 1;                   // mask sums are exact ints
        tot += startT[tg[0]] + endT[tg[last]];
        g_num[b] = tot;
    }
}

// ---------------------------------------------------------------------------
// Deterministic fixed-tree reduction: mean(den - num) over B
// ---------------------------------------------------------------------------
__global__ void crf_reduce_kernel(float* __restrict__ out) {
    __shared__ double sh[256];
    int tid = threadIdx.x;
    double v = 0.0;
    for (int i = tid; i < BB; i += 256)
        v += (double)g_den[i] - (double)g_num[i];
    sh[tid] = v;
    __syncthreads();
    for (int o = 128; o > 0; o >>= 1) {
        if (tid < o) sh[tid] += sh[tid + o];
        __syncthreads();
    }
    if (tid == 0) out[0] = (float)(sh[0] / (double)BB);
}

extern "C" void kernel_launch(void* const* d_in, const int* in_sizes, int n_in,
                              void* d_out, int out_size) {
    const float* em     = (const float*)d_in[0];
    const int*   tags   = (const int*)  d_in[1];
    const float* mask   = (const float*)d_in[2];
    const float* trans  = (const float*)d_in[3];
    const float* startT = (const float*)d_in[4];
    const float* endT   = (const float*)d_in[5];

    crf_prep_kernel<<<(KK * KK + 255) / 256, 256>>>(trans);
    crf_main_kernel<<<BB / CPB, CPB * KK>>>(em, tags, mask, trans, startT, endT);
    crf_reduce_kernel<<<1, 256>>>((float*)d_out);
}

// round 2
// speedup vs baseline: 1.2830x; 1.2830x over previous
#include <cuda_runtime.h>
#include <cuda_bf16.h>
#include <cstdint>

#define BB 1024
#define TT 512
#define KK 48
#define CPB 2   // chains per block

typedef unsigned long long u64;

// Scratch (static __device__ globals: allocation-free per harness rules)
__device__ float g_expTt[KK * KK];  // [j][i] = exp(trans[i][j]) (transposed)
__device__ float g_den[BB];
__device__ float g_num[BB];

// ---------------------------------------------------------------------------
__global__ void crf_prep_kernel(const float* __restrict__ trans) {
    int idx = blockIdx.x * blockDim.x + threadIdx.x;
    if (idx < KK * KK) {
        int j = idx / KK;
        int i = idx - j * KK;
        g_expTt[idx] = expf(trans[i * KK + j]);
    }
}

// packed f32x2 helpers (sm_103a)
__device__ __forceinline__ u64 fma2(u64 a, u64 b, u64 c) {
    u64 d; asm("fma.rn.f32x2 %0, %1, %2, %3;" : "=l"(d) : "l"(a), "l"(b), "l"(c));
    return d;
}
__device__ __forceinline__ u64 add2(u64 a, u64 b) {
    u64 d; asm("add.rn.f32x2 %0, %1, %2;" : "=l"(d) : "l"(a), "l"(b));
    return d;
}

// ---------------------------------------------------------------------------
// Forward recurrence in the linear domain with lag-2 renormalization.
// alpha_j(t) = C2*ln2 + ln(q_j). One __syncthreads per step.
// ---------------------------------------------------------------------------
__global__ __launch_bounds__(CPB * KK) void crf_main_kernel(
    const float* __restrict__ em,      // [B,T,K]
    const int*   __restrict__ tags,    // [B,T]
    const float* __restrict__ mask,    // [B,T]
    const float* __restrict__ trans,   // [K,K]
    const float* __restrict__ startT,  // [K]
    const float* __restrict__ endT)    // [K]
{
    const int c = threadIdx.x / KK;
    const int j = threadIdx.x - c * KK;
    const int b = blockIdx.x * CPB + c;

    __shared__ __align__(16) float sh_p[CPB][2][KK];   // double-buffered p
    __shared__ float sh_lq0[CPB][2];                   // lag-2 offsets
    __shared__ float sh_red[CPB][KK];
    __shared__ float sh_red2[CPB][KK];

    const float* emb = em   + (size_t)b * TT * KK;
    const float* mkb = mask + (size_t)b * TT;

    // exp(T[i][j]) column for output state j, packed as 24 f32x2 pairs
    u64 ET2[KK / 2];
    {
        const u64* et = (const u64*)g_expTt + j * (KK / 2);
#pragma unroll
        for (int i = 0; i < KK / 2; i++) ET2[i] = et[i];
    }

    const float LOG2E = 1.4426950408889634f;
    const float LN2   = 0.6931471805599453f;

    uint32_t sp_base;
    {
        const float* p0 = &sh_p[c][0][0];
        asm("{ .reg .u64 t; cvta.to.shared.u64 t, %1; cvt.u32.u64 %0, t; }"
            : "=r"(sp_base) : "l"(p0));
    }

    // init: alpha0 = start + emissions[:,0]; renormalize vs thread 0
    float a0 = startT[j] + emb[j];
    sh_red[c][j] = a0;
    if (j == 0) { sh_lq0[c][0] = 0.f; sh_lq0[c][1] = 0.f; }
    __syncthreads();
    float ref = sh_red[c][0];
    float q   = exp2f((a0 - ref) * LOG2E);
    float C2  = ref * LOG2E;   // running offset, log2 domain
    float comp = 0.f;          // Kahan compensation

    float e_next  = emb[KK + j];
    float mk_next = mkb[1];

#pragma unroll 2
    for (int t = 1; t < TT; t++) {
        const int buf = t & 1;
        float e = e_next, mk = mk_next;
        int tn = (t + 1 < TT) ? (t + 1) : (TT - 1);
        e_next  = emb[tn * KK + j];        // prefetch
        mk_next = mkb[tn];

        float lq0 = sh_lq0[c][buf];                    // offset from t-2
        float p = q * exp2f(fmaf(e, LOG2E, -lq0));     // one EX2 on the path
        sh_p[c][buf][j] = p;
        __syncthreads();                               // single barrier/step

        // matvec: acc_j = sum_i p_i * expT[i][j]   (12 LDS.128 + 24 FFMA2)
        uint32_t addr = sp_base + (uint32_t)buf * (KK * 4);
        u64 A0 = 0ull, A1 = 0ull, A2 = 0ull, A3 = 0ull;
#pragma unroll
        for (int i = 0; i < KK / 4; i++) {
            u64 lo, hi;
            asm volatile("ld.shared.v2.b64 {%0,%1},[%2];"
                         : "=l"(lo), "=l"(hi) : "r"(addr + 16u * i));
            if (i & 1) { A2 = fma2(lo, ET2[2 * i], A2); A3 = fma2(hi, ET2[2 * i + 1], A3); }
            else       { A0 = fma2(lo, ET2[2 * i], A0); A1 = fma2(hi, ET2[2 * i + 1], A1); }
        }
        u64 S = add2(add2(A0, A1), add2(A2, A3));
        float slo, shi;
        asm("mov.b64 {%0,%1}, %2;" : "=f"(slo), "=f"(shi) : "l"(S));
        float acc = slo + shi;

        // C2 += lq0 (Kahan, identical on all threads of the chain)
        float y  = lq0 - comp;
        float s2 = C2 + y;
        comp = (s2 - C2) - y;
        C2 = s2;

        q = acc;
        if (mk == 0.f) { q = 1.f; C2 = 0.f; comp = 0.f; }  // alpha *= mask
        if (j == 0) sh_lq0[c][buf] = log2f(q);             // publish for t+2
    }

    // log_den[b] = C2*ln2 + LSE_j(ln q_j + end_j)
    sh_red[c][j] = log2f(q) * LN2 + endT[j];
    __syncthreads();
    if (j == 0) {
        float mm = sh_red[c][0];
#pragma unroll
        for (int i = 1; i < KK; i++) mm = fmaxf(mm, sh_red[c][i]);
        float ss = 0.f;
#pragma unroll
        for (int i = 0; i < KK; i++) ss += exp2f((sh_red[c][i] - mm) * LOG2E);
        double den = (double)C2 * 0.6931471805599453
                   + (double)mm
                   + (double)log2f(ss) * 0.6931471805599453;
        g_den[b] = (float)den;
    }
    __syncthreads();

    // log_num[b]: gold path score
    const int* tg = tags + (size_t)b * TT;
    float part = 0.f, msum = 0.f;
    for (int t = j; t < TT - 1; t += KK) {
        int t0 = tg[t], t1 = tg[t + 1];
        part += emb[t * KK + t0];
        part += trans[t0 * KK + t1] * mkb[t + 1];
    }
    for (int t = j; t < TT; t += KK) msum += mkb[t];
    sh_red[c][j] = part;
    sh_red2[c][j] = msum;
    __syncthreads();
    if (j == 0) {
        float tot = 0.f, mtot = 0.f;
        for (int i = 0; i < KK; i++) { tot += sh_red[c][i]; mtot += sh_red2[c][i]; }
        int last = (int)mtot - 1;
        tot += startT[tg[0]] + endT[tg[last]];
        g_num[b] = tot;
    }
}

// ---------------------------------------------------------------------------
__global__ void crf_reduce_kernel(float* __restrict__ out) {
    __shared__ double sh[256];
    int tid = threadIdx.x;
    double v = 0.0;
    for (int i = tid; i < BB; i += 256)
        v += (double)g_den[i] - (double)g_num[i];
    sh[tid] = v;
    __syncthreads();
    for (int o = 128; o > 0; o >>= 1) {
        if (tid < o) sh[tid] += sh[tid + o];
        __syncthreads();
    }
    if (tid == 0) out[0] = (float)(sh[0] / (double)BB);
}

extern "C" void kernel_launch(void* const* d_in, const int* in_sizes, int n_in,
                              void* d_out, int out_size) {
    const float* em     = (const float*)d_in[0];
    const int*   tags   = (const int*)  d_in[1];
    const float* mask   = (const float*)d_in[2];
    const float* trans  = (const float*)d_in[3];
    const float* startT = (const float*)d_in[4];
    const float* endT   = (const float*)d_in[5];

    crf_prep_kernel<<<(KK * KK + 255) / 256, 256>>>(trans);
    crf_main_kernel<<<BB / CPB, CPB * KK>>>(em, tags, mask, trans, startT, endT);
    crf_reduce_kernel<<<1, 256>>>((float*)d_out);
}

// round 3
// speedup vs baseline: 1.3697x; 1.0675x over previous
#include <cuda_runtime.h>
#include <cuda_bf16.h>
#include <cstdint>

#define BB 1024
#define TT 512
#define KK 48
#define WPB 4   // warps (= chains) per block

typedef unsigned long long u64;

__device__ float g_expTt[KK * KK];  // [j][i] = exp(trans[i][j])
__device__ float g_den[BB];
__device__ float g_num[BB];

__global__ void crf_prep_kernel(const float* __restrict__ trans) {
    int idx = blockIdx.x * blockDim.x + threadIdx.x;
    if (idx < KK * KK) {
        int j = idx / KK;
        int i = idx - j * KK;
        g_expTt[idx] = expf(trans[i * KK + j]);
    }
}

__device__ __forceinline__ u64 fma2(u64 a, u64 b, u64 c) {
    u64 d; asm("fma.rn.f32x2 %0, %1, %2, %3;" : "=l"(d) : "l"(a), "l"(b), "l"(c));
    return d;
}
__device__ __forceinline__ u64 add2(u64 a, u64 b) {
    u64 d; asm("add.rn.f32x2 %0, %1, %2;" : "=l"(d) : "l"(a), "l"(b));
    return d;
}

// ---------------------------------------------------------------------------
// One warp per chain. 24 lanes own state pairs (2l, 2l+1). No __syncthreads.
// alpha_j(t) = ln2 * (C2 + log2 q_j), lag-2 renormalization via shfl.
// ---------------------------------------------------------------------------
__global__ __launch_bounds__(WPB * 32) void crf_main_kernel(
    const float* __restrict__ em,      // [B,T,K]
    const int*   __restrict__ tags,    // [B,T]
    const float* __restrict__ mask,    // [B,T]
    const float* __restrict__ trans,   // [K,K]
    const float* __restrict__ startT,  // [K]
    const float* __restrict__ endT)    // [K]
{
    const int lane = threadIdx.x & 31;
    const int w    = threadIdx.x >> 5;
    const int b    = blockIdx.x * WPB + w;
    const int l    = (lane < 24) ? lane : 0;    // pair index (clamped)
    const bool act = (lane < 24);

    __shared__ __align__(16) float sh_p[WPB][2][KK];  // warp-private, dbl-buffered

    const float* emb = em   + (size_t)b * TT * KK;
    const float* mkb = mask + (size_t)b * TT;

    // ET columns for output states 2l, 2l+1: u64 pairs over input index i
    u64 ETa[24], ETb[24];
    {
        const u64* rowA = (const u64*)(g_expTt + (2 * l)     * KK);
        const u64* rowB = (const u64*)(g_expTt + (2 * l + 1) * KK);
#pragma unroll
        for (int k = 0; k < 24; k++) { ETa[k] = rowA[k]; ETb[k] = rowB[k]; }
    }

    const float LOG2E = 1.4426950408889634f;
    const float LN2   = 0.6931471805599453f;

    uint32_t spb;
    {
        const float* p0 = &sh_p[w][0][0];
        asm("{ .reg .u64 t; cvta.to.shared.u64 t, %1; cvt.u32.u64 %0, t; }"
            : "=r"(spb) : "l"(p0));
    }

    // init: alpha0 = start + emissions[:,0], renormalized by state 0
    float2 st = ((const float2*)startT)[l];
    float2 e0 = ((const float2*)emb)[l];
    float aLo = st.x + e0.x, aHi = st.y + e0.y;
    float ref = __shfl_sync(0xffffffffu, aLo, 0);
    float qLo = exp2f((aLo - ref) * LOG2E);
    float qHi = exp2f((aHi - ref) * LOG2E);
    float C2 = ref * LOG2E, comp = 0.f;
    float lqA = 0.f, lqB = 0.f;   // lag-2 offsets for odd/even steps

    float2 e_next  = ((const float2*)(emb + KK))[l];
    float  mk_next = mkb[1];

#pragma unroll 2
    for (int t = 1; t < TT; t++) {
        const int buf = t & 1;
        float2 e = e_next;
        float mk = mk_next;
        int tn = (t + 1 < TT) ? (t + 1) : (TT - 1);
        e_next  = ((const float2*)(emb + tn * KK))[l];   // prefetch
        mk_next = mkb[tn];

        float lq = buf ? lqB : lqA;                      // offset from t-2
        float pLo = qLo * exp2f(fmaf(e.x, LOG2E, -lq));
        float pHi = qHi * exp2f(fmaf(e.y, LOG2E, -lq));
        if (act) {
            uint32_t sa = spb + (uint32_t)buf * (KK * 4) + (uint32_t)l * 8;
            asm volatile("st.shared.v2.f32 [%0], {%1,%2};"
                         :: "r"(sa), "f"(pLo), "f"(pHi));
        }
        __syncwarp();

        // matvec: cols 2l and 2l+1, 12 LDS.128 + 48 FFMA2, 8 accumulators
        uint32_t addr = spb + (uint32_t)buf * (KK * 4);
        u64 A0 = 0, A1 = 0, A2 = 0, A3 = 0;
        u64 B0 = 0, B1 = 0, B2 = 0, B3 = 0;
#pragma unroll
        for (int k = 0; k < 12; k++) {
            u64 lo, hi;
            asm volatile("ld.shared.v2.b64 {%0,%1},[%2];"
                         : "=l"(lo), "=l"(hi) : "r"(addr + 16u * k));
            int m = 2 * k;
            switch (m & 3) {
              case 0: A0 = fma2(lo, ETa[m], A0); B0 = fma2(lo, ETb[m], B0);
                      A1 = fma2(hi, ETa[m+1], A1); B1 = fma2(hi, ETb[m+1], B1); break;
              default:A2 = fma2(lo, ETa[m], A2); B2 = fma2(lo, ETb[m], B2);
                      A3 = fma2(hi, ETa[m+1], A3); B3 = fma2(hi, ETb[m+1], B3); break;
            }
        }
        u64 SA = add2(add2(A0, A1), add2(A2, A3));
        u64 SB = add2(add2(B0, B1), add2(B2, B3));
        float ax, ay, bx, by;
        asm("mov.b64 {%0,%1}, %2;" : "=f"(ax), "=f"(ay) : "l"(SA));
        asm("mov.b64 {%0,%1}, %2;" : "=f"(bx), "=f"(by) : "l"(SB));
        qLo = ax + ay;          // new q for state 2l
        qHi = bx + by;          // new q for state 2l+1

        // C2 += lq (Kahan; identical across lanes)
        float y  = lq - comp;
        float s2 = C2 + y;
        comp = (s2 - C2) - y;
        C2 = s2;

        if (mk == 0.f) { qLo = 1.f; qHi = 1.f; C2 = 0.f; comp = 0.f; }

        // publish log2(q_state0) for step t+2 (same parity)
        float lg  = log2f(qLo);
        float lgb = __shfl_sync(0xffffffffu, lg, 0);
        if (buf) lqB = lgb; else lqA = lgb;
    }

    // log_den[b] = C2*ln2 + LSE_j(ln q_j + end_j)   (warp shfl reduction)
    {
        float2 en = ((const float2*)endT)[l];
        float vLo = log2f(qLo) * LN2 + en.x;
        float vHi = log2f(qHi) * LN2 + en.y;
        if (!act) { vLo = -3.0e38f; vHi = -3.0e38f; }
        float m = fmaxf(vLo, vHi);
#pragma unroll
        for (int o = 16; o > 0; o >>= 1)
            m = fmaxf(m, __shfl_xor_sync(0xffffffffu, m, o));
        float s = act ? (exp2f((vLo - m) * LOG2E) + exp2f((vHi - m) * LOG2E)) : 0.f;
#pragma unroll
        for (int o = 16; o > 0; o >>= 1)
            s += __shfl_xor_sync(0xffffffffu, s, o);
        if (lane == 0) {
            double den = (double)C2 * 0.6931471805599453
                       + (double)m
                       + (double)log2f(s) * 0.6931471805599453;
            g_den[b] = (float)den;
        }
    }

    // log_num[b]: gold path score (all 32 lanes stride over t)
    {
        const int* tg = tags + (size_t)b * TT;
        float part = 0.f, msum = 0.f;
        for (int t = lane; t < TT - 1; t += 32) {
            int t0 = tg[t], t1 = tg[t + 1];
            part += emb[t * KK + t0];
            part += trans[t0 * KK + t1] * mkb[t + 1];
        }
        for (int t = lane; t < TT; t += 32) msum += mkb[t];
#pragma unroll
        for (int o = 16; o > 0; o >>= 1) {
            part += __shfl_xor_sync(0xffffffffu, part, o);
            msum += __shfl_xor_sync(0xffffffffu, msum, o);
        }
        if (lane == 0) {
            int last = (int)msum - 1;
            g_num[b] = part + startT[tg[0]] + endT[tg[last]];
        }
    }
}

__global__ void crf_reduce_kernel(float* __restrict__ out) {
    __shared__ double sh[256];
    int tid = threadIdx.x;
    double v = 0.0;
    for (int i = tid; i < BB; i += 256)
        v += (double)g_den[i] - (double)g_num[i];
    sh[tid] = v;
    __syncthreads();
    for (int o = 128; o > 0; o >>= 1) {
        if (tid < o) sh[tid] += sh[tid + o];
        __syncthreads();
    }
    if (tid == 0) out[0] = (float)(sh[0] / (double)BB);
}

extern "C" void kernel_launch(void* const* d_in, const int* in_sizes, int n_in,
                              void* d_out, int out_size) {
    const float* em     = (const float*)d_in[0];
    const int*   tags   = (const int*)  d_in[1];
    const float* mask   = (const float*)d_in[2];
    const float* trans  = (const float*)d_in[3];
    const float* startT = (const float*)d_in[4];
    const float* endT   = (const float*)d_in[5];

    crf_prep_kernel<<<(KK * KK + 255) / 256, 256>>>(trans);
    crf_main_kernel<<<BB / WPB, WPB * 32>>>(em, tags, mask, trans, startT, endT);
    crf_reduce_kernel<<<1, 256>>>((float*)d_out);
}

// round 4
// speedup vs baseline: 1.5835x; 1.1561x over previous
#include <cuda_runtime.h>
#include <cuda_bf16.h>
#include <cstdint>

#define BB 1024
#define TT 512
#define KK 48
#define WPB 4   // warps (= chains) per block
#define PFD 4   // emission prefetch depth (steps)

typedef unsigned long long u64;

__device__ float g_expTt[KK * KK];  // [j][i] = exp(trans[i][j])
__device__ float g_den[BB];
__device__ float g_num[BB];

__global__ void crf_prep_kernel(const float* __restrict__ trans) {
    int idx = blockIdx.x * blockDim.x + threadIdx.x;
    if (idx < KK * KK) {
        int j = idx / KK;
        int i = idx - j * KK;
        g_expTt[idx] = expf(trans[i * KK + j]);
    }
}

__device__ __forceinline__ u64 fma2(u64 a, u64 b, u64 c) {
    u64 d; asm("fma.rn.f32x2 %0, %1, %2, %3;" : "=l"(d) : "l"(a), "l"(b), "l"(c));
    return d;
}
__device__ __forceinline__ u64 add2(u64 a, u64 b) {
    u64 d; asm("add.rn.f32x2 %0, %1, %2;" : "=l"(d) : "l"(a), "l"(b));
    return d;
}

#define LOG2E 1.4426950408889634f
#define LN2   0.6931471805599453f

// One recurrence step. e/mk supplied from deep prefetch queue.
__device__ __forceinline__ void crf_step(
    float2 e, float mk, int buf, uint32_t spb,
    const u64* __restrict__ ETa, const u64* __restrict__ ETb,
    float& qLo, float& qHi, float& C2, float& comp,
    float& lqA, float& lqB, bool act, int l)
{
    float lq = buf ? lqB : lqA;                  // lag-2 offset
    float pLo = qLo * exp2f(fmaf(e.x, LOG2E, -lq));
    float pHi = qHi * exp2f(fmaf(e.y, LOG2E, -lq));
    if (act) {
        uint32_t sa = spb + (uint32_t)buf * (KK * 4) + (uint32_t)l * 8;
        asm volatile("st.shared.v2.f32 [%0], {%1,%2};" :: "r"(sa), "f"(pLo), "f"(pHi));
    }
    __syncwarp();

    uint32_t addr = spb + (uint32_t)buf * (KK * 4);
    u64 A0 = 0, A1 = 0, A2 = 0, A3 = 0;
    u64 B0 = 0, B1 = 0, B2 = 0, B3 = 0;
#pragma unroll
    for (int k = 0; k < 12; k++) {
        u64 lo, hi;
        asm volatile("ld.shared.v2.b64 {%0,%1},[%2];"
                     : "=l"(lo), "=l"(hi) : "r"(addr + 16u * k));
        const int m = 2 * k;
        if ((k & 1) == 0) {
            A0 = fma2(lo, ETa[m], A0);     B0 = fma2(lo, ETb[m], B0);
            A1 = fma2(hi, ETa[m + 1], A1); B1 = fma2(hi, ETb[m + 1], B1);
        } else {
            A2 = fma2(lo, ETa[m], A2);     B2 = fma2(lo, ETb[m], B2);
            A3 = fma2(hi, ETa[m + 1], A3); B3 = fma2(hi, ETb[m + 1], B3);
        }
    }
    u64 SA = add2(add2(A0, A1), add2(A2, A3));
    u64 SB = add2(add2(B0, B1), add2(B2, B3));
    float ax, ay, bx, by;
    asm("mov.b64 {%0,%1}, %2;" : "=f"(ax), "=f"(ay) : "l"(SA));
    asm("mov.b64 {%0,%1}, %2;" : "=f"(bx), "=f"(by) : "l"(SB));
    qLo = ax + ay;
    qHi = bx + by;

    float y  = lq - comp;                        // Kahan: C2 += lq
    float s2 = C2 + y;
    comp = (s2 - C2) - y;
    C2 = s2;

    if (mk == 0.f) { qLo = 1.f; qHi = 1.f; C2 = 0.f; comp = 0.f; }

    float lg  = log2f(qLo);                      // publish for t+2
    float lgb = __shfl_sync(0xffffffffu, lg, 0);
    if (buf) lqB = lgb; else lqA = lgb;
}

// ---------------------------------------------------------------------------
__global__ __launch_bounds__(WPB * 32) void crf_main_kernel(
    const float* __restrict__ em,      // [B,T,K]
    const int*   __restrict__ tags,    // [B,T]
    const float* __restrict__ mask,    // [B,T]
    const float* __restrict__ trans,   // [K,K]
    const float* __restrict__ startT,  // [K]
    const float* __restrict__ endT)    // [K]
{
    const int lane = threadIdx.x & 31;
    const int w    = threadIdx.x >> 5;
    const int b    = blockIdx.x * WPB + w;
    const int l    = (lane < 24) ? lane : 0;
    const bool act = (lane < 24);

    __shared__ __align__(16) float sh_p[WPB][2][KK];

    const float* emb = em   + (size_t)b * TT * KK;
    const float* mkb = mask + (size_t)b * TT;
    const float2* emb2 = (const float2*)emb;

    u64 ETa[24], ETb[24];
    {
        const u64* rowA = (const u64*)(g_expTt + (2 * l)     * KK);
        const u64* rowB = (const u64*)(g_expTt + (2 * l + 1) * KK);
#pragma unroll
        for (int k = 0; k < 24; k++) { ETa[k] = rowA[k]; ETb[k] = rowB[k]; }
    }

    uint32_t spb;
    {
        const float* p0 = &sh_p[w][0][0];
        asm("{ .reg .u64 t; cvta.to.shared.u64 t, %1; cvt.u32.u64 %0, t; }"
            : "=r"(spb) : "l"(p0));
    }

    // init
    float2 st = ((const float2*)startT)[l];
    float2 e0 = emb2[l];
    float aLo = st.x + e0.x, aHi = st.y + e0.y;
    float ref = __shfl_sync(0xffffffffu, aLo, 0);
    float qLo = exp2f((aLo - ref) * LOG2E);
    float qHi = exp2f((aHi - ref) * LOG2E);
    float C2 = ref * LOG2E, comp = 0.f;
    float lqA = 0.f, lqB = 0.f;

    // depth-PFD prefetch queues for steps t = 1..PFD
    float2 Eq[PFD];
    float  Mq[PFD];
#pragma unroll
    for (int d = 0; d < PFD; d++) {
        int tt = 1 + d; if (tt > TT - 1) tt = TT - 1;
        Eq[d] = emb2[tt * (KK / 2) + l];
        Mq[d] = mkb[tt];
    }

    int t = 1;
    // main blocks of PFD steps; t..t+PFD-1 all valid while t+PFD-1 <= TT-1
#pragma unroll 1
    for (; t + PFD - 1 <= TT - 1; t += PFD) {
#pragma unroll
        for (int d = 0; d < PFD; d++) {
            const int tt = t + d;                    // current step (compile-time d)
            float2 e = Eq[d];
            float mk = Mq[d];
            int tp = tt + PFD; if (tp > TT - 1) tp = TT - 1;   // refill slot d
            Eq[d] = emb2[tp * (KK / 2) + l];
            Mq[d] = mkb[tp];
            crf_step(e, mk, tt & 1, spb, ETa, ETb,
                     qLo, qHi, C2, comp, lqA, lqB, act, l);
        }
    }
    // tail (< PFD steps): queue still holds them at slots (t+d-1)%PFD... simpler: direct loads
#pragma unroll 1
    for (; t < TT; t++) {
        float2 e = emb2[t * (KK / 2) + l];
        float mk = mkb[t];
        crf_step(e, mk, t & 1, spb, ETa, ETb,
                 qLo, qHi, C2, comp, lqA, lqB, act, l);
    }

    // log_den[b] = C2*ln2 + LSE_j(ln q_j + end_j)
    {
        float2 en = ((const float2*)endT)[l];
        float vLo = log2f(qLo) * LN2 + en.x;
        float vHi = log2f(qHi) * LN2 + en.y;
        if (!act) { vLo = -3.0e38f; vHi = -3.0e38f; }
        float m = fmaxf(vLo, vHi);
#pragma unroll
        for (int o = 16; o > 0; o >>= 1)
            m = fmaxf(m, __shfl_xor_sync(0xffffffffu, m, o));
        float s = act ? (exp2f((vLo - m) * LOG2E) + exp2f((vHi - m) * LOG2E)) : 0.f;
#pragma unroll
        for (int o = 16; o > 0; o >>= 1)
            s += __shfl_xor_sync(0xffffffffu, s, o);
        if (lane == 0) {
            double den = (double)C2 * 0.6931471805599453
                       + (double)m
                       + (double)log2f(s) * 0.6931471805599453;
            g_den[b] = (float)den;
        }
    }

    // log_num[b]
    {
        const int* tg = tags + (size_t)b * TT;
        float part = 0.f, msum = 0.f;
        for (int tt = lane; tt < TT - 1; tt += 32) {
            int t0 = tg[tt], t1 = tg[tt + 1];
            part += emb[tt * KK + t0];
            part += trans[t0 * KK + t1] * mkb[tt + 1];
        }
        for (int tt = lane; tt < TT; tt += 32) msum += mkb[tt];
#pragma unroll
        for (int o = 16; o > 0; o >>= 1) {
            part += __shfl_xor_sync(0xffffffffu, part, o);
            msum += __shfl_xor_sync(0xffffffffu, msum, o);
        }
        if (lane == 0) {
            int last = (int)msum - 1;
            g_num[b] = part + startT[tg[0]] + endT[tg[last]];
        }
    }
}

__global__ void crf_reduce_kernel(float* __restrict__ out) {
    __shared__ double sh[256];
    int tid = threadIdx.x;
    double v = 0.0;
    for (int i = tid; i < BB; i += 256)
        v += (double)g_den[i] - (double)g_num[i];
    sh[tid] = v;
    __syncthreads();
    for (int o = 128; o > 0; o >>= 1) {
        if (tid < o) sh[tid] += sh[tid + o];
        __syncthreads();
    }
    if (tid == 0) out[0] = (float)(sh[0] / (double)BB);
}

extern "C" void kernel_launch(void* const* d_in, const int* in_sizes, int n_in,
                              void* d_out, int out_size) {
    const float* em     = (const float*)d_in[0];
    const int*   tags   = (const int*)  d_in[1];
    const float* mask   = (const float*)d_in[2];
    const float* trans  = (const float*)d_in[3];
    const float* startT = (const float*)d_in[4];
    const float* endT   = (const float*)d_in[5];

    crf_prep_kernel<<<(KK * KK + 255) / 256, 256>>>(trans);
    crf_main_kernel<<<BB / WPB, WPB * 32>>>(em, tags, mask, trans, startT, endT);
    crf_reduce_kernel<<<1, 256>>>((float*)d_out);
}